// round 7
// baseline (speedup 1.0000x reference)
#include <cuda_runtime.h>
#include <cuda_fp16.h>

// ---------------------------------------------------------------------------
// Collapsed TemporalGNN (H0 == 0 in the scan; R gate dead):
//   y    = A_hat x           (pull-gather via per-dst buckets, no atomics)
//   Hn   = (1 + tanh(-(y@Mz + cz)/2)) * tanh(y@Mh + ch) * 0.5
//   acc  = sum_t p_t * Hn ;  out = relu(acc) @ head_w + head_b
// deg[d] == cnt[d] + 1 (self loops). Pipeline:
//   k_init : zero cnt + fused weights + softmax
//   k_work : edge fill (srcs+counts)  ||  transpose x -> xT[node][b][24]
//   k_norm : per-entry norm = rsqrt(cnt[d]+1)*rsqrt(cnt[s]+1) into bucket
//   k_fused: gather (contiguous 384B/src) -> shuffle -> packed node math -> head
// ---------------------------------------------------------------------------

#define NB 4
#define NT 12
#define NN 30000
#define NH 32
#define NO 12
#define NE 240000
#define NODE_W 24               /* F_IN(2) * T(12) floats per (b,node) */
#define NQ (NODE_W / 4)
#define CAP 64
#define CNT_BLOCKS ((NN + 255) / 256)
#define FILL_BLOCKS ((NE + 255) / 256)
#define TRQ (NB * NN * NQ)      /* 720000 float4 to transpose */
#define TR_BLOCKS ((TRQ + 255) / 256)

typedef unsigned long long u64;

__device__ int   g_cnt[NN];
__device__ uint2 g_bkt[(size_t)NN * CAP];     // (src, bitcast norm)
__device__ float g_xT[(size_t)NN * NB * NODE_W];  // node-major x
__device__ float g_Mz[2 * NH];                // NEGATED, x0.5
__device__ float g_Mh[2 * NH];
__device__ float g_cz[NH];                    // NEGATED, x0.5
__device__ float g_ch[NH];
__device__ float g_p[NT];                     // softmax * 0.5

// ---- packed-math helpers ----
__device__ __forceinline__ u64 pk(float lo, float hi) {
    u64 r; asm("mov.b64 %0, {%1, %2};" : "=l"(r) : "f"(lo), "f"(hi)); return r;
}
__device__ __forceinline__ void upk(u64 v, float& lo, float& hi) {
    asm("mov.b64 {%0, %1}, %2;" : "=f"(lo), "=f"(hi) : "l"(v));
}
__device__ __forceinline__ u64 fma2(u64 a, u64 b, u64 c) {
    u64 r; asm("fma.rn.f32x2 %0, %1, %2, %3;" : "=l"(r) : "l"(a), "l"(b), "l"(c));
    return r;
}
__device__ __forceinline__ u64 add2(u64 a, u64 b) {
    u64 r; asm("add.rn.f32x2 %0, %1, %2;" : "=l"(r) : "l"(a), "l"(b)); return r;
}
__device__ __forceinline__ unsigned cvt2(float lo, float hi) {   // -> f16x2
    unsigned r; asm("cvt.rn.f16x2.f32 %0, %1, %2;" : "=r"(r) : "f"(hi), "f"(lo));
    return r;
}
__device__ __forceinline__ unsigned tanh2(unsigned x) {
    unsigned r; asm("tanh.approx.f16x2 %0, %1;" : "=r"(r) : "r"(x)); return r;
}
__device__ __forceinline__ unsigned hfma2u(unsigned a, unsigned b, unsigned c) {
    unsigned r; asm("fma.rn.f16x2 %0, %1, %2, %3;" : "=r"(r) : "r"(a), "r"(b), "r"(c));
    return r;
}

// Blocks [0, CNT_BLOCKS): cnt = 0. Block CNT_BLOCKS: fused weights + softmax.
__global__ void k_init(const float* __restrict__ att,
                       const float* __restrict__ czw, const float* __restrict__ czb,
                       const float* __restrict__ lzw, const float* __restrict__ lzb,
                       const float* __restrict__ chw, const float* __restrict__ chb,
                       const float* __restrict__ lhw, const float* __restrict__ lhb) {
    if (blockIdx.x < CNT_BLOCKS) {
        int i = blockIdx.x * 256 + threadIdx.x;
        if (i < NN) g_cnt[i] = 0;
        return;
    }
    int lane = threadIdx.x & 31;
    int warp = threadIdx.x >> 5;

    if (threadIdx.x == 0) {
        float m = -1e30f;
        for (int i = 0; i < NT; i++) m = fmaxf(m, att[i]);
        float e[NT], s = 0.f;
        for (int i = 0; i < NT; i++) { e[i] = __expf(att[i] - m); s += e[i]; }
        float inv = 0.5f / s;                    // fold the 0.5 of (1-tz)/2 here
        for (int i = 0; i < NT; i++) g_p[i] = e[i] * inv;
    }

#pragma unroll
    for (int i = warp; i < 2 * NH; i += 8) {
        int gate = i >> 5;                       // 0 = z gate, 1 = h gate
        int h = i & 31;
        const float* cw = gate ? chw : czw;
        const float* cb = gate ? chb : czb;
        const float* lw = gate ? lhw : lzw;
        const float* lb = gate ? lhb : lzb;
        float w = lw[lane * NH + h];             // only first NH rows matter (H0=0)
        float m0 = cw[lane] * w;
        float m1 = cw[NH + lane] * w;
        float c  = cb[lane] * w;
#pragma unroll
        for (int off = 16; off; off >>= 1) {
            m0 += __shfl_xor_sync(0xffffffffu, m0, off);
            m1 += __shfl_xor_sync(0xffffffffu, m1, off);
            c  += __shfl_xor_sync(0xffffffffu, c, off);
        }
        if (lane == 0) {
            c += lb[h];
            if (gate == 0) {                     // negate: tanh(-az/2) = -tz
                g_Mz[h] = -0.5f * m0; g_Mz[NH + h] = -0.5f * m1; g_cz[h] = -0.5f * c;
            } else {
                g_Mh[h] = m0; g_Mh[NH + h] = m1; g_ch[h] = c;
            }
        }
    }
}

// Blocks [0, FILL_BLOCKS): edge fill. Rest: transpose x -> xT[n][b][24].
__global__ void k_work(const int* __restrict__ ei, const float* __restrict__ x) {
    if (blockIdx.x < FILL_BLOCKS) {
        int e = blockIdx.x * 256 + threadIdx.x;
        if (e >= NE) return;
        int s = __ldg(ei + e);
        int d = __ldg(ei + NE + e);
        int pos = atomicAdd(&g_cnt[d], 1);
        ((unsigned*)g_bkt)[((size_t)d * CAP + pos) * 2] = (unsigned)s;
        return;
    }
    int tid = (blockIdx.x - FILL_BLOCKS) * 256 + threadIdx.x;   // float4 id
    if (tid >= TRQ) return;
    int q = tid % NQ;
    int b = (tid / NQ) & 3;
    int n = tid / (NQ * NB);
    ((float4*)g_xT)[tid] = __ldg((const float4*)x + ((size_t)b * NN + n) * NQ + q);
}

// Per-entry norms: warp per node, lane per bucket entry. Fully parallel
// scattered loads with no downstream dependency.
__global__ void k_norm() {
    int n    = blockIdx.x * 8 + (threadIdx.x >> 5);
    int lane = threadIdx.x & 31;
    int cnt  = g_cnt[n];
    float dinv = rsqrtf((float)(cnt + 1));
    for (int i = lane; i < cnt; i += 32) {
        unsigned s = ((unsigned*)g_bkt)[((size_t)n * CAP + i) * 2];
        float nm = dinv * rsqrtf((float)(g_cnt[s] + 1));
        ((unsigned*)g_bkt)[((size_t)n * CAP + i) * 2 + 1] = __float_as_uint(nm);
    }
}

// Fused gather + node compute + head GEMV. One warp per node, all 4 batches.
__global__ void __launch_bounds__(256)
k_fused(const float* __restrict__ hw, const float* __restrict__ hb,
        float* __restrict__ out) {
    __shared__ u64 s_Mz0[16], s_Mz1[16], s_czp[16];
    __shared__ u64 s_Mh0[16], s_Mh1[16], s_chp[16];
    __shared__ u64 s_hwp[NH * NO / 2];
    __shared__ u64 s_hbp[NO / 2];
    __shared__ unsigned s_ph[NT];
    int tid = threadIdx.x;
    if (tid < 16) {
        s_Mz0[tid] = pk(g_Mz[2 * tid], g_Mz[2 * tid + 1]);
        s_Mz1[tid] = pk(g_Mz[NH + 2 * tid], g_Mz[NH + 2 * tid + 1]);
        s_czp[tid] = pk(g_cz[2 * tid], g_cz[2 * tid + 1]);
        s_Mh0[tid] = pk(g_Mh[2 * tid], g_Mh[2 * tid + 1]);
        s_Mh1[tid] = pk(g_Mh[NH + 2 * tid], g_Mh[NH + 2 * tid + 1]);
        s_chp[tid] = pk(g_ch[2 * tid], g_ch[2 * tid + 1]);
    }
    if (tid < NT) {
        __half2 h2 = __float2half2_rn(g_p[tid]);
        s_ph[tid] = *(unsigned*)&h2;
    }
    for (int i = tid; i < NH * NO / 2; i += 256) s_hwp[i] = ((const u64*)hw)[i];
    if (tid < NO / 2) s_hbp[tid] = ((const u64*)hb)[tid];
    __syncthreads();

    int n    = blockIdx.x * 8 + (tid >> 5);       // NN % 8 == 0
    int lane = tid & 31;

    // -------- gather phase: 24 active lanes; xT row = 384B contiguous ------
    bool act = lane < 24;
    int   cnt  = g_cnt[n];
    float dinv = rsqrtf((float)(cnt + 1));
    const uint4*  bp4 = (const uint4*)(g_bkt + (size_t)n * CAP);
    const float4* xT4 = (const float4*)g_xT;

    float4 acc = make_float4(0.f, 0.f, 0.f, 0.f);
    if (act) {
        float4 xs = __ldg(xT4 + (size_t)n * 24 + lane);
        float inv = dinv * dinv;                  // 1/deg self-loop weight
        acc.x = xs.x * inv; acc.y = xs.y * inv;
        acc.z = xs.z * inv; acc.w = xs.w * inv;
    }

    int rc = (cnt + 3) >> 2;
    for (int g = 0; g < rc; g++) {
        uint4 pa = bp4[2 * g];                    // entries 4g, 4g+1 (uniform)
        uint4 pb = bp4[2 * g + 1];                // entries 4g+2, 4g+3
        int base = 4 * g;
        float n0 = __uint_as_float(pa.y);
        float n1 = (base + 1 < cnt) ? __uint_as_float(pa.w) : 0.f;
        float n2 = (base + 2 < cnt) ? __uint_as_float(pb.y) : 0.f;
        float n3 = (base + 3 < cnt) ? __uint_as_float(pb.w) : 0.f;
        if (act) {
            float4 v0 = __ldg(xT4 + (size_t)pa.x * 24 + lane);
            float4 v1 = __ldg(xT4 + (size_t)pa.z * 24 + lane);
            float4 v2 = __ldg(xT4 + (size_t)pb.x * 24 + lane);
            float4 v3 = __ldg(xT4 + (size_t)pb.z * 24 + lane);
            acc.x = fmaf(n0, v0.x, acc.x); acc.y = fmaf(n0, v0.y, acc.y);
            acc.z = fmaf(n0, v0.z, acc.z); acc.w = fmaf(n0, v0.w, acc.w);
            acc.x = fmaf(n1, v1.x, acc.x); acc.y = fmaf(n1, v1.y, acc.y);
            acc.z = fmaf(n1, v1.z, acc.z); acc.w = fmaf(n1, v1.w, acc.w);
            acc.x = fmaf(n2, v2.x, acc.x); acc.y = fmaf(n2, v2.y, acc.y);
            acc.z = fmaf(n2, v2.z, acc.z); acc.w = fmaf(n2, v2.w, acc.w);
            acc.x = fmaf(n3, v3.x, acc.x); acc.y = fmaf(n3, v3.y, acc.y);
            acc.z = fmaf(n3, v3.z, acc.z); acc.w = fmaf(n3, v3.w, acc.w);
        }
    }

    // -------- redistribute via shuffles: lane = b*8 + r, r in [0,8) --------
    // xT ordering: gather lane = b*6 + q, component j%4 of y[b][q*4+j].
    float ar[4] = {acc.x, acc.y, acc.z, acc.w};
    int r  = lane & 7;
    int bb = lane >> 3;
    float ya[NT], yb[NT];
#pragma unroll
    for (int t = 0; t < NT; t++) {
        ya[t] = __shfl_sync(0xffffffffu, ar[t & 3], bb * 6 + (t >> 2));
        yb[t] = __shfl_sync(0xffffffffu, ar[t & 3], bb * 6 + 3 + (t >> 2));
    }

    // -------- node phase: lane handles h-pairs 2r, 2r+1 --------------------
    int k0 = 2 * r;
    u64 mz0A = s_Mz0[k0], mz1A = s_Mz1[k0], czA = s_czp[k0];
    u64 mh0A = s_Mh0[k0], mh1A = s_Mh1[k0], chA = s_chp[k0];
    u64 mz0B = s_Mz0[k0 + 1], mz1B = s_Mz1[k0 + 1], czB = s_czp[k0 + 1];
    u64 mh0B = s_Mh0[k0 + 1], mh1B = s_Mh1[k0 + 1], chB = s_chp[k0 + 1];
    unsigned ph_[NT];
#pragma unroll
    for (int t = 0; t < NT; t++) ph_[t] = s_ph[t];

    unsigned accA = 0, accB = 0;
#pragma unroll
    for (int t = 0; t < NT; t++) {
        u64 a2 = pk(ya[t], ya[t]);
        u64 b2 = pk(yb[t], yb[t]);
        u64 aznA = fma2(a2, mz0A, fma2(b2, mz1A, czA));
        u64 ahpA = fma2(a2, mh0A, fma2(b2, mh1A, chA));
        u64 aznB = fma2(a2, mz0B, fma2(b2, mz1B, czB));
        u64 ahpB = fma2(a2, mh0B, fma2(b2, mh1B, chB));
        float zl, zh, hl, hh;
        upk(aznA, zl, zh); upk(ahpA, hl, hh);
        unsigned tznA = tanh2(cvt2(zl, zh));
        unsigned thA  = tanh2(cvt2(hl, hh));
        upk(aznB, zl, zh); upk(ahpB, hl, hh);
        unsigned tznB = tanh2(cvt2(zl, zh));
        unsigned thB  = tanh2(cvt2(hl, hh));
        accA = hfma2u(ph_[t], hfma2u(tznA, thA, thA), accA);
        accB = hfma2u(ph_[t], hfma2u(tznB, thB, thB), accB);
    }

    // -------- head GEMV + butterfly over 8 lanes ---------------------------
    __half2 hA = *(__half2*)&accA, hB = *(__half2*)&accB;
    float r0 = fmaxf(__low2float(hA), 0.f);
    float r1 = fmaxf(__high2float(hA), 0.f);
    float r2 = fmaxf(__low2float(hB), 0.f);
    float r3 = fmaxf(__high2float(hB), 0.f);
    u64 r02 = pk(r0, r0), r12 = pk(r1, r1), r22 = pk(r2, r2), r32 = pk(r3, r3);
    const u64* w0 = &s_hwp[(4 * r + 0) * (NO / 2)];
    const u64* w1 = &s_hwp[(4 * r + 1) * (NO / 2)];
    const u64* w2 = &s_hwp[(4 * r + 2) * (NO / 2)];
    const u64* w3 = &s_hwp[(4 * r + 3) * (NO / 2)];
    u64 o2[NO / 2];
#pragma unroll
    for (int j = 0; j < NO / 2; j++)
        o2[j] = fma2(r02, w0[j], fma2(r12, w1[j], fma2(r22, w2[j], fma2(r32, w3[j], 0ULL))));

#pragma unroll
    for (int off = 1; off < 8; off <<= 1) {
#pragma unroll
        for (int j = 0; j < NO / 2; j++)
            o2[j] = add2(o2[j], __shfl_xor_sync(0xffffffffu, o2[j], off));
    }

    if (r < 3) {
        float4 v;
        upk(add2(o2[2 * r], s_hbp[2 * r]), v.x, v.y);
        upk(add2(o2[2 * r + 1], s_hbp[2 * r + 1]), v.z, v.w);
        ((float4*)out)[((size_t)bb * NN + n) * 3 + r] = v;
    }
}

extern "C" void kernel_launch(void* const* d_in, const int* in_sizes, int n_in,
                              void* d_out, int out_size) {
    const float* x   = (const float*)d_in[0];
    const int*   ei  = (const int*)d_in[1];
    const float* att = (const float*)d_in[2];
    const float* czw = (const float*)d_in[3];
    const float* czb = (const float*)d_in[4];
    const float* lzw = (const float*)d_in[5];
    const float* lzb = (const float*)d_in[6];
    // d_in[7..10] = conv_r_*, lin_r_* : dead (H0 == 0 -> H0*R == 0)
    const float* chw = (const float*)d_in[11];
    const float* chb = (const float*)d_in[12];
    const float* lhw = (const float*)d_in[13];
    const float* lhb = (const float*)d_in[14];
    const float* hw  = (const float*)d_in[15];
    const float* hb  = (const float*)d_in[16];
    float* out = (float*)d_out;

    k_init<<<CNT_BLOCKS + 1, 256>>>(att, czw, czb, lzw, lzb, chw, chb, lhw, lhb);
    k_work<<<FILL_BLOCKS + TR_BLOCKS, 256>>>(ei, x);
    k_norm<<<NN / 8, 256>>>();
    k_fused<<<NN / 8, 256>>>(hw, hb, out);
}

// round 8
// speedup vs baseline: 1.1421x; 1.1421x over previous
#include <cuda_runtime.h>
#include <cuda_fp16.h>

// ---------------------------------------------------------------------------
// Collapsed TemporalGNN (H0 == 0 in the scan; R gate dead):
//   y    = A_hat x           (pull-gather via per-dst buckets, no atomics)
//   Hn   = (1 + tanh(-(y@Mz + cz)/2)) * tanh(y@Mh + ch) * 0.5
//   acc  = sum_t p_t * Hn ;  out = relu(acc) @ head_w + head_b
// deg[d] == cnt[d] + 1 (self loops). 3-kernel pipeline:
//   k_work  : edge fill || transpose x -> xT[n][b][24] || fused weights
//   k_gather: bucket row -> registers, parallel norm prefetch, shuffled
//             (src,norm) + contiguous 384B gathers -> g_y (b-major)
//   k_node  : packed node math + head GEMV; re-zeroes g_cnt for next replay
// g_cnt starts zeroed (module load) and is re-zeroed by k_node each call.
// ---------------------------------------------------------------------------

#define NB 4
#define NT 12
#define NN 30000
#define NH 32
#define NO 12
#define NE 240000
#define NODE_W 24               /* F_IN(2) * T(12) floats per (b,node) */
#define NQ (NODE_W / 4)
#define CAP 64
#define FILL_BLOCKS ((NE + 255) / 256)
#define TRQ (NB * NN * NQ)      /* 720000 float4 to transpose */
#define TR_BLOCKS ((TRQ + 255) / 256)

typedef unsigned long long u64;

__device__ int      g_cnt[NN];                    // zero-init; re-zeroed by k_node
__device__ unsigned g_bkt[(size_t)NN * CAP];      // src ids
__device__ float g_xT[(size_t)NN * NB * NODE_W];  // node-major x
__device__ float g_y[(size_t)NB * NN * NODE_W];   // batch-major aggregated
__device__ float g_Mz[2 * NH];                    // NEGATED, x0.5
__device__ float g_Mh[2 * NH];
__device__ float g_cz[NH];                        // NEGATED, x0.5
__device__ float g_ch[NH];
__device__ float g_p[NT];                         // softmax * 0.5

// ---- packed-math helpers ----
__device__ __forceinline__ u64 pk(float lo, float hi) {
    u64 r; asm("mov.b64 %0, {%1, %2};" : "=l"(r) : "f"(lo), "f"(hi)); return r;
}
__device__ __forceinline__ void upk(u64 v, float& lo, float& hi) {
    asm("mov.b64 {%0, %1}, %2;" : "=f"(lo), "=f"(hi) : "l"(v));
}
__device__ __forceinline__ u64 fma2(u64 a, u64 b, u64 c) {
    u64 r; asm("fma.rn.f32x2 %0, %1, %2, %3;" : "=l"(r) : "l"(a), "l"(b), "l"(c));
    return r;
}
__device__ __forceinline__ unsigned cvt2(float lo, float hi) {   // -> f16x2
    unsigned r; asm("cvt.rn.f16x2.f32 %0, %1, %2;" : "=r"(r) : "f"(hi), "f"(lo));
    return r;
}
__device__ __forceinline__ unsigned tanh2(unsigned x) {
    unsigned r; asm("tanh.approx.f16x2 %0, %1;" : "=r"(r) : "r"(x)); return r;
}
__device__ __forceinline__ unsigned hfma2u(unsigned a, unsigned b, unsigned c) {
    unsigned r; asm("fma.rn.f16x2 %0, %1, %2, %3;" : "=r"(r) : "r"(a), "r"(b), "r"(c));
    return r;
}

// Blocks [0, FILL_BLOCKS): edge fill. [FILL, FILL+TR): transpose.
// Last block: fused weights + softmax.
__global__ void k_work(const int* __restrict__ ei, const float* __restrict__ x,
                       const float* __restrict__ att,
                       const float* __restrict__ czw, const float* __restrict__ czb,
                       const float* __restrict__ lzw, const float* __restrict__ lzb,
                       const float* __restrict__ chw, const float* __restrict__ chb,
                       const float* __restrict__ lhw, const float* __restrict__ lhb) {
    if (blockIdx.x < FILL_BLOCKS) {
        int e = blockIdx.x * 256 + threadIdx.x;
        if (e >= NE) return;
        int s = __ldg(ei + e);
        int d = __ldg(ei + NE + e);
        int pos = atomicAdd(&g_cnt[d], 1);
        g_bkt[(size_t)d * CAP + pos] = (unsigned)s;
        return;
    }
    if (blockIdx.x < FILL_BLOCKS + TR_BLOCKS) {
        int tid = (blockIdx.x - FILL_BLOCKS) * 256 + threadIdx.x;  // float4 id
        if (tid >= TRQ) return;
        int q = tid % NQ;
        int b = (tid / NQ) & 3;
        int n = tid / (NQ * NB);
        ((float4*)g_xT)[tid] = __ldg((const float4*)x + ((size_t)b * NN + n) * NQ + q);
        return;
    }
    // ---- weights block ----
    int lane = threadIdx.x & 31;
    int warp = threadIdx.x >> 5;
    if (threadIdx.x == 0) {
        float m = -1e30f;
        for (int i = 0; i < NT; i++) m = fmaxf(m, att[i]);
        float e[NT], s = 0.f;
        for (int i = 0; i < NT; i++) { e[i] = __expf(att[i] - m); s += e[i]; }
        float inv = 0.5f / s;                    // fold the 0.5 of (1-tz)/2 here
        for (int i = 0; i < NT; i++) g_p[i] = e[i] * inv;
    }
#pragma unroll
    for (int i = warp; i < 2 * NH; i += 8) {
        int gate = i >> 5;                       // 0 = z gate, 1 = h gate
        int h = i & 31;
        const float* cw = gate ? chw : czw;
        const float* cb = gate ? chb : czb;
        const float* lw = gate ? lhw : lzw;
        const float* lb = gate ? lhb : lzb;
        float w = lw[lane * NH + h];             // only first NH rows matter (H0=0)
        float m0 = cw[lane] * w;
        float m1 = cw[NH + lane] * w;
        float c  = cb[lane] * w;
#pragma unroll
        for (int off = 16; off; off >>= 1) {
            m0 += __shfl_xor_sync(0xffffffffu, m0, off);
            m1 += __shfl_xor_sync(0xffffffffu, m1, off);
            c  += __shfl_xor_sync(0xffffffffu, c, off);
        }
        if (lane == 0) {
            c += lb[h];
            if (gate == 0) {                     // negate: tanh(-az/2) = -tz
                g_Mz[h] = -0.5f * m0; g_Mz[NH + h] = -0.5f * m1; g_cz[h] = -0.5f * c;
            } else {
                g_Mh[h] = m0; g_Mh[NH + h] = m1; g_ch[h] = c;
            }
        }
    }
}

// Gather: one warp per node. Bucket row loaded once into registers (s0/s1),
// norms prefetched with one parallel scattered load, then the gather loop
// uses shuffles only + 4 independent contiguous 384B gathers per group.
__global__ void __launch_bounds__(256)
k_gather() {
    int n    = blockIdx.x * 8 + (threadIdx.x >> 5);   // NN % 8 == 0
    int lane = threadIdx.x & 31;

    int   cnt  = g_cnt[n];
    float dinv = rsqrtf((float)(cnt + 1));            // deg = cnt + 1
    const unsigned* brow = g_bkt + (size_t)n * CAP;

    unsigned s0 = (lane < cnt) ? brow[lane] : 0u;                 // coalesced
    unsigned s1 = (lane + 32 < cnt) ? brow[lane + 32] : 0u;
    float nm0 = (lane < cnt) ? dinv * rsqrtf((float)(g_cnt[s0] + 1)) : 0.f;
    float nm1 = (lane + 32 < cnt) ? dinv * rsqrtf((float)(g_cnt[s1] + 1)) : 0.f;

    bool act = lane < 24;
    int q = lane % 6;
    int b = act ? (lane / 6) : 0;
    const float4* xT4 = (const float4*)g_xT;

    float4 acc = make_float4(0.f, 0.f, 0.f, 0.f);
    if (act) {
        float4 xs = __ldg(xT4 + (size_t)n * 24 + lane);
        float inv = dinv * dinv;                      // self-loop weight 1/deg
        acc.x = xs.x * inv; acc.y = xs.y * inv;
        acc.z = xs.z * inv; acc.w = xs.w * inv;
    }

    for (int e = 0; e < cnt; e += 4) {
        // (src, norm) via register shuffles — uniform indices, no memory.
        unsigned c0, c1, c2, c3; float n0, n1, n2, n3;
        if (e < 32) {
            c0 = __shfl_sync(0xffffffffu, s0, e);
            c1 = __shfl_sync(0xffffffffu, s0, (e + 1) & 31);
            c2 = __shfl_sync(0xffffffffu, s0, (e + 2) & 31);
            c3 = __shfl_sync(0xffffffffu, s0, (e + 3) & 31);
            n0 = __shfl_sync(0xffffffffu, nm0, e);
            n1 = __shfl_sync(0xffffffffu, nm0, (e + 1) & 31);
            n2 = __shfl_sync(0xffffffffu, nm0, (e + 2) & 31);
            n3 = __shfl_sync(0xffffffffu, nm0, (e + 3) & 31);
            if (e + 1 >= 32) { c1 = __shfl_sync(0xffffffffu, s1, 0); n1 = __shfl_sync(0xffffffffu, nm1, 0); }
            if (e + 2 >= 32) { c2 = __shfl_sync(0xffffffffu, s1, (e + 2) - 32); n2 = __shfl_sync(0xffffffffu, nm1, (e + 2) - 32); }
            if (e + 3 >= 32) { c3 = __shfl_sync(0xffffffffu, s1, (e + 3) - 32); n3 = __shfl_sync(0xffffffffu, nm1, (e + 3) - 32); }
        } else {
            c0 = __shfl_sync(0xffffffffu, s1, e - 32);
            c1 = __shfl_sync(0xffffffffu, s1, e - 31);
            c2 = __shfl_sync(0xffffffffu, s1, e - 30);
            c3 = __shfl_sync(0xffffffffu, s1, e - 29);
            n0 = __shfl_sync(0xffffffffu, nm1, e - 32);
            n1 = __shfl_sync(0xffffffffu, nm1, e - 31);
            n2 = __shfl_sync(0xffffffffu, nm1, e - 30);
            n3 = __shfl_sync(0xffffffffu, nm1, e - 29);
        }
        // tail masking: norms beyond cnt forced to 0 (src values are valid ids)
        if (e + 1 >= cnt) n1 = 0.f;
        if (e + 2 >= cnt) n2 = 0.f;
        if (e + 3 >= cnt) n3 = 0.f;
        if (act) {
            float4 v0 = __ldg(xT4 + (size_t)c0 * 24 + lane);
            float4 v1 = __ldg(xT4 + (size_t)c1 * 24 + lane);
            float4 v2 = __ldg(xT4 + (size_t)c2 * 24 + lane);
            float4 v3 = __ldg(xT4 + (size_t)c3 * 24 + lane);
            acc.x = fmaf(n0, v0.x, acc.x); acc.y = fmaf(n0, v0.y, acc.y);
            acc.z = fmaf(n0, v0.z, acc.z); acc.w = fmaf(n0, v0.w, acc.w);
            acc.x = fmaf(n1, v1.x, acc.x); acc.y = fmaf(n1, v1.y, acc.y);
            acc.z = fmaf(n1, v1.z, acc.z); acc.w = fmaf(n1, v1.w, acc.w);
            acc.x = fmaf(n2, v2.x, acc.x); acc.y = fmaf(n2, v2.y, acc.y);
            acc.z = fmaf(n2, v2.z, acc.z); acc.w = fmaf(n2, v2.w, acc.w);
            acc.x = fmaf(n3, v3.x, acc.x); acc.y = fmaf(n3, v3.y, acc.y);
            acc.z = fmaf(n3, v3.z, acc.z); acc.w = fmaf(n3, v3.w, acc.w);
        }
    }
    if (act) ((float4*)g_y)[((size_t)b * NN + n) * NQ + q] = acc;
}

// Pointwise collapse + head GEMV. One thread per (b, node).
// First blocks also re-zero g_cnt for the next graph replay.
__global__ void __launch_bounds__(256)
k_node(const float* __restrict__ hw, const float* __restrict__ hb,
       float* __restrict__ out) {
    __shared__ u64 s_Mz0[16], s_Mz1[16], s_czp[16];
    __shared__ u64 s_Mh0[16], s_Mh1[16], s_chp[16];
    __shared__ u64 s_hwp[NH * NO / 2];
    __shared__ u64 s_hbp[NO / 2];
    __shared__ unsigned s_ph[NT];
    int tid = threadIdx.x;
    int gid = blockIdx.x * 256 + tid;

    if (gid < NN) g_cnt[gid] = 0;                 // reset for next replay

    if (tid < 16) {
        s_Mz0[tid] = pk(g_Mz[2 * tid], g_Mz[2 * tid + 1]);
        s_Mz1[tid] = pk(g_Mz[NH + 2 * tid], g_Mz[NH + 2 * tid + 1]);
        s_czp[tid] = pk(g_cz[2 * tid], g_cz[2 * tid + 1]);
        s_Mh0[tid] = pk(g_Mh[2 * tid], g_Mh[2 * tid + 1]);
        s_Mh1[tid] = pk(g_Mh[NH + 2 * tid], g_Mh[NH + 2 * tid + 1]);
        s_chp[tid] = pk(g_ch[2 * tid], g_ch[2 * tid + 1]);
    }
    if (tid < NT) {
        __half2 h2 = __float2half2_rn(g_p[tid]);
        s_ph[tid] = *(unsigned*)&h2;
    }
    for (int i = tid; i < NH * NO / 2; i += 256) s_hwp[i] = ((const u64*)hw)[i];
    if (tid < NO / 2) s_hbp[tid] = ((const u64*)hb)[tid];
    __syncthreads();

    if (gid >= NB * NN) return;

    float yv[NODE_W];
    const float4* yp4 = (const float4*)(g_y + (size_t)gid * NODE_W);
#pragma unroll
    for (int i = 0; i < NQ; i++) {
        float4 v = yp4[i];
        yv[4 * i] = v.x; yv[4 * i + 1] = v.y; yv[4 * i + 2] = v.z; yv[4 * i + 3] = v.w;
    }
    u64 a2[NT], b2[NT];
#pragma unroll
    for (int t = 0; t < NT; t++) { a2[t] = pk(yv[t], yv[t]); b2[t] = pk(yv[NT + t], yv[NT + t]); }
    unsigned ph_[NT];
#pragma unroll
    for (int t = 0; t < NT; t++) ph_[t] = s_ph[t];

    u64 o2[NO / 2];
#pragma unroll
    for (int j = 0; j < NO / 2; j++) o2[j] = s_hbp[j];

#pragma unroll 1
    for (int k = 0; k < 16; k++) {                // h-pair index
        u64 mz0 = s_Mz0[k], mz1 = s_Mz1[k], czc = s_czp[k];
        u64 mh0 = s_Mh0[k], mh1 = s_Mh1[k], chc = s_chp[k];
        unsigned acc = 0;                         // half2 zero
#pragma unroll
        for (int t = 0; t < NT; t++) {
            u64 azn = fma2(a2[t], mz0, fma2(b2[t], mz1, czc));  // = -(az)/2 pair
            u64 ahp = fma2(a2[t], mh0, fma2(b2[t], mh1, chc));
            float zl, zh, hl, hh;
            upk(azn, zl, zh); upk(ahp, hl, hh);
            unsigned tzn = tanh2(cvt2(zl, zh));   // = -tz (odd fn, consts negated)
            unsigned th  = tanh2(cvt2(hl, hh));
            unsigned u   = hfma2u(tzn, th, th);   // (1 - tz) * th
            acc = hfma2u(ph_[t], u, acc);
        }
        __half2 ah2 = *(__half2*)&acc;
        float rl = fmaxf(__low2float(ah2), 0.f);  // relu, h = 2k
        float rh = fmaxf(__high2float(ah2), 0.f); // h = 2k+1
        u64 rl2 = pk(rl, rl), rh2 = pk(rh, rh);
        const u64* w0 = &s_hwp[(2 * k) * (NO / 2)];
        const u64* w1 = &s_hwp[(2 * k + 1) * (NO / 2)];
#pragma unroll
        for (int j = 0; j < NO / 2; j++)
            o2[j] = fma2(rl2, w0[j], fma2(rh2, w1[j], o2[j]));
    }

    float of[NO];
#pragma unroll
    for (int j = 0; j < NO / 2; j++) upk(o2[j], of[2 * j], of[2 * j + 1]);
    float4* op4 = (float4*)(out + (size_t)gid * NO);
#pragma unroll
    for (int j = 0; j < NO / 4; j++)
        op4[j] = make_float4(of[4 * j], of[4 * j + 1], of[4 * j + 2], of[4 * j + 3]);
}

extern "C" void kernel_launch(void* const* d_in, const int* in_sizes, int n_in,
                              void* d_out, int out_size) {
    const float* x   = (const float*)d_in[0];
    const int*   ei  = (const int*)d_in[1];
    const float* att = (const float*)d_in[2];
    const float* czw = (const float*)d_in[3];
    const float* czb = (const float*)d_in[4];
    const float* lzw = (const float*)d_in[5];
    const float* lzb = (const float*)d_in[6];
    // d_in[7..10] = conv_r_*, lin_r_* : dead (H0 == 0 -> H0*R == 0)
    const float* chw = (const float*)d_in[11];
    const float* chb = (const float*)d_in[12];
    const float* lhw = (const float*)d_in[13];
    const float* lhb = (const float*)d_in[14];
    const float* hw  = (const float*)d_in[15];
    const float* hb  = (const float*)d_in[16];
    float* out = (float*)d_out;

    k_work<<<FILL_BLOCKS + TR_BLOCKS + 1, 256>>>(ei, x, att, czw, czb, lzw, lzb,
                                                 chw, chb, lhw, lhb);
    k_gather<<<NN / 8, 256>>>();
    k_node<<<(NB * NN + 255) / 256, 256>>>(hw, hb, out);
}